// round 1
// baseline (speedup 1.0000x reference)
#include <cuda_runtime.h>
#include <math.h>

#define NS   2048
#define D    512
#define LYR  8
#define MAXN 64
#define KTOP 5

// ---------------- device scratch (no allocations allowed) ----------------
__device__ float g_invn[LYR * NS];
__device__ float g_num[LYR - 1];
__device__ float g_den[LYR - 1];
__device__ int   g_is64;

// ---------------- kernel 1: inverse norms + init ----------------
__global__ void prep_kernel(const float* __restrict__ feats,
                            const int*   __restrict__ sids32) {
    if (blockIdx.x == 0) {
        if (threadIdx.x < LYR - 1) { g_num[threadIdx.x] = 0.f; g_den[threadIdx.x] = 0.f; }
        if (threadIdx.x == 0) {
            // sample_ids = arange(2048). int64 -> int32 words [0,0,1,0,2,0,...];
            // int32 -> [0,1,2,3,...]. word[2]==1 iff int64.
            g_is64 = (sids32[2] == 1) ? 1 : 0;
        }
    }
    int warp = (blockIdx.x * blockDim.x + threadIdx.x) >> 5;
    int lane = threadIdx.x & 31;
    if (warp >= LYR * NS) return;
    const float4* row = (const float4*)(feats + (size_t)warp * D);
    float ss = 0.f;
#pragma unroll
    for (int k = 0; k < 4; k++) {
        float4 v = row[lane + 32 * k];
        ss += v.x * v.x + v.y * v.y + v.z * v.z + v.w * v.w;
    }
#pragma unroll
    for (int o = 16; o; o >>= 1) ss += __shfl_xor_sync(0xffffffffu, ss, o);
    if (lane == 0) g_invn[warp] = 1.0f / fmaxf(sqrtf(ss), 1e-8f);
}

// ---------------- warp-per-pair cosine block into shared ----------------
__device__ __forceinline__ void compute_sims(const float* __restrict__ F,
                                             const float* __restrict__ invn,
                                             const int* idx, int n, float* sim) {
    const int w     = threadIdx.x >> 5;
    const int lane  = threadIdx.x & 31;
    const int nwarp = blockDim.x >> 5;
    const int npair = n * (n + 1) / 2;
    for (int p = w; p < npair; p += nwarp) {
        int i = (int)((sqrtf(8.0f * (float)p + 1.0f) - 1.0f) * 0.5f);
        while ((i + 1) * (i + 2) / 2 <= p) i++;
        while (i * (i + 1) / 2 > p) i--;
        int j = p - i * (i + 1) / 2;
        int gi = idx[i], gj = idx[j];
        const float4* a = (const float4*)(F + (size_t)gi * D);
        const float4* b = (const float4*)(F + (size_t)gj * D);
        float dot = 0.f;
#pragma unroll
        for (int k = 0; k < 4; k++) {
            float4 x = a[lane + 32 * k];
            float4 y = b[lane + 32 * k];
            dot += x.x * y.x + x.y * y.y + x.z * y.z + x.w * y.w;
        }
#pragma unroll
        for (int o = 16; o; o >>= 1) dot += __shfl_xor_sync(0xffffffffu, dot, o);
        if (lane == 0) {
            // float32 clip bounds (-1+1e-8, 1-1e-8) round to exactly (-1, 1)
            float s = dot * invn[gi] * invn[gj];
            s = fminf(fmaxf(s, -1.0f), 1.0f);
            sim[i * MAXN + j] = s;
            sim[j * MAXN + i] = s;
        }
    }
}

// top-5 with jax.lax.top_k tie-break (equal values -> lower index wins):
// ascending scan with strict '>' reproduces this exactly.
__device__ __forceinline__ void top5_row(const float* row, int n, int self, int* ch) {
#pragma unroll
    for (int t = 0; t < KTOP; t++) {
        float bv = 0.f;   // only strictly-positive sims are candidates
        int   bj = -1;
        for (int j = 0; j < n; j++) {
            if (j == self) continue;
            bool used = false;
            for (int u = 0; u < t; u++) if (ch[u] == j) used = true;
            if (used) continue;
            float v = row[j];
            if (v > bv) { bv = v; bj = j; }
        }
        ch[t] = bj;
    }
}

__device__ __forceinline__ int get_label(const int* lab, int i, int is64) {
    return is64 ? lab[2 * i] : lab[i];
}

// ---------------- kernel 2: one CTA per class, whole pipeline ----------------
__global__ __launch_bounds__(256) void pga_kernel(const float* __restrict__ feats,
                                                  const int*   __restrict__ labels) {
    const int cls  = blockIdx.x;
    const int tid  = threadIdx.x;
    const int is64 = g_is64;

    __shared__ int           mem[MAXN];
    __shared__ int           sub[MAXN];
    __shared__ float         simbuf[2][MAXN * MAXN];
    __shared__ unsigned char mbuf[2][MAXN * MAXN];
    __shared__ float         emabuf[2][MAXN];
    __shared__ unsigned char keep[MAXN];
    __shared__ unsigned char insub[MAXN];
    __shared__ int           scan[256];
    __shared__ int           sn, sn2;

    // ---- build sorted (ascending global index) member list for this class ----
    int loc[8];
    int c = 0;
    int base = tid * 8;
#pragma unroll
    for (int k = 0; k < 8; k++) {
        int gi = base + k;
        if (get_label(labels, gi, is64) == cls) loc[c++] = gi;
    }
    scan[tid] = c;
    __syncthreads();
    for (int off = 1; off < 256; off <<= 1) {
        int v = (tid >= off) ? scan[tid - off] : 0;
        __syncthreads();
        scan[tid] += v;
        __syncthreads();
    }
    int start = scan[tid] - c;
    for (int k = 0; k < c; k++) {
        int pos = start + k;
        if (pos < MAXN) mem[pos] = loc[k];
    }
    if (tid == 255) sn = (scan[255] < MAXN) ? scan[255] : MAXN;
    __syncthreads();
    const int n = sn;
    if (n == 0) return;

    // ---- phase A: layer-7 knn on the FULL class -> subset membership ----
    {
        const float* F    = feats  + (size_t)(LYR - 1) * NS * D;
        const float* invn = g_invn + (LYR - 1) * NS;
        compute_sims(F, invn, mem, n, simbuf[0]);
        __syncthreads();
        if (tid < n) {
            insub[tid] = 0;
            const float* row = simbuf[0] + tid * MAXN;
            int cand = 0;
            for (int j = 0; j < n; j++)
                if (j != tid && row[j] > 0.f) cand++;
            keep[tid] = (cand >= KTOP) ? 1 : 0;
        }
        __syncthreads();
        if (tid < n && keep[tid]) {
            const float* row = simbuf[0] + tid * MAXN;
            int ch[KTOP];
            top5_row(row, n, tid, ch);
#pragma unroll
            for (int t = 0; t < KTOP; t++) {
                int j = ch[t];
                if (j >= 0 && keep[j]) { insub[tid] = 1; insub[j] = 1; }  // benign race
            }
        }
        __syncthreads();
        if (tid == 0) {
            int m = 0;
            for (int i = 0; i < n; i++)
                if (insub[i]) sub[m++] = mem[i];
            sn2 = m;
        }
        __syncthreads();
    }
    const int n2 = sn2;
    if (n2 == 0) return;

    // ---- phase B: per-layer knn/A/ema on the subset; pair accumulation ----
    for (int l = 0; l < LYR; l++) {
        float*         simCur  = simbuf[l & 1];
        float*         simPrev = simbuf[(l & 1) ^ 1];
        unsigned char* mCur    = mbuf[l & 1];
        unsigned char* mPrev   = mbuf[(l & 1) ^ 1];
        float*         emaCur  = emabuf[l & 1];
        float*         emaPrev = emabuf[(l & 1) ^ 1];

        const float* F    = feats  + (size_t)l * NS * D;
        const float* invn = g_invn + l * NS;
        compute_sims(F, invn, sub, n2, simCur);
        for (int p = tid; p < n2 * n2; p += 256)
            mCur[(p / n2) * MAXN + (p % n2)] = 0;
        __syncthreads();

        if (tid < n2) {
            const float* row = simCur + tid * MAXN;
            float rs = 0.f;
            int dg = 0, cand = 0;
            for (int j = 0; j < n2; j++) {
                float v = row[j];
                if (v > 0.f) { rs += v; dg++; if (j != tid) cand++; }
            }
            float degf  = (float)(dg > 0 ? dg : 1);
            float score = 1.0f / (1.0f + expf(-rs / degf));
            emaCur[tid] = 0.45f + 0.1f * score;        // MOM*0.5 + (1-MOM)*score
            keep[tid]   = (cand >= KTOP) ? 1 : 0;
        }
        __syncthreads();
        if (tid < n2 && keep[tid]) {
            const float* row = simCur + tid * MAXN;
            int ch[KTOP];
            top5_row(row, n2, tid, ch);
#pragma unroll
            for (int t = 0; t < KTOP; t++) {
                int j = ch[t];
                if (j >= 0 && keep[j]) mCur[tid * MAXN + j] = 1;
            }
        }
        __syncthreads();

        if (l > 0) {
            float pnum = 0.f, pden = 0.f;
            for (int p = tid; p < n2 * n2; p += 256) {
                int i = p / n2, j = p % n2;
                if (i == j) continue;
                int ml = mPrev[i * MAXN + j] | mPrev[j * MAXN + i];  // symmetrized masks
                int mc = mCur [i * MAXN + j] | mCur [j * MAXN + i];
                if (ml | mc) {
                    float w  = emaPrev[i] * emaPrev[j];
                    float al = ml ? simPrev[i * MAXN + j] : 0.f;     // A = sim * M
                    float ac = mc ? simCur [i * MAXN + j] : 0.f;
                    float d  = ac - al;
                    pnum += d * d * w;
                    pden += w;
                }
            }
#pragma unroll
            for (int o = 16; o; o >>= 1) {
                pnum += __shfl_xor_sync(0xffffffffu, pnum, o);
                pden += __shfl_xor_sync(0xffffffffu, pden, o);
            }
            if ((tid & 31) == 0 && (pnum != 0.f || pden != 0.f)) {
                atomicAdd(&g_num[l - 1], pnum);
                atomicAdd(&g_den[l - 1], pden);
            }
        }
        __syncthreads();
    }
}

// ---------------- kernel 3: combine ----------------
__global__ void final_kernel(float* out) {
    if (blockIdx.x == 0 && threadIdx.x == 0) {
        float raw = 0.f;
        for (int t = 0; t < LYR - 1; t++) {
            if (g_den[t] > 0.f)                       // M_eff.sum() > 0  <=>  any edge
                raw += g_num[t] / fmaxf(g_den[t], 1e-8f);
        }
        out[0] = 16.0f * (raw / 7.0f);                // LAMBDA_ALIGN_K * raw / (L-1)
    }
}

extern "C" void kernel_launch(void* const* d_in, const int* in_sizes, int n_in,
                              void* d_out, int out_size) {
    const float* feats  = (const float*)d_in[0];
    const int*   labels = (const int*)d_in[1];   // int32 or int64; detected at runtime
    const int*   sids   = (const int*)d_in[2];
    float*       out    = (float*)d_out;

    prep_kernel<<<2048, 256>>>(feats, sids);
    pga_kernel<<<128, 256>>>(feats, labels);
    final_kernel<<<1, 32>>>(out);
}

// round 2
// speedup vs baseline: 3.1176x; 3.1176x over previous
#include <cuda_runtime.h>
#include <math.h>

#define NS   2048
#define D    512
#define D4   128
#define LYR  8
#define NCLS 128
#define MAXN 64
#define SCAP 32          // rows staged in shared; beyond -> global fallback
#define KTOP 5

// ---------------- device scratch (no allocations allowed) ----------------
__device__ float         g_invn[LYR * NS];
__device__ int           g_is64;
__device__ int           g_sub[NCLS * MAXN];
__device__ int           g_n2[NCLS];
__device__ float         g_sim[(size_t)LYR * NCLS * MAXN * MAXN];   // 16.8 MB
__device__ unsigned char g_msk[(size_t)LYR * NCLS * MAXN * MAXN];   // 4.2 MB
__device__ float         g_w[LYR * NCLS * MAXN];
__device__ float         g_num[LYR - 1];
__device__ float         g_den[LYR - 1];

// ---------------- kernel 1: inverse norms + init ----------------
__global__ void prep_kernel(const float* __restrict__ feats,
                            const int*   __restrict__ sids32) {
    if (blockIdx.x == 0) {
        if (threadIdx.x < LYR - 1) { g_num[threadIdx.x] = 0.f; g_den[threadIdx.x] = 0.f; }
        if (threadIdx.x == 0) {
            // sample_ids = arange. int64 -> int32 words [0,0,1,0,...]; word[2]==1 iff int64
            g_is64 = (sids32[2] == 1) ? 1 : 0;
        }
    }
    int warp = (blockIdx.x * blockDim.x + threadIdx.x) >> 5;
    int lane = threadIdx.x & 31;
    if (warp >= LYR * NS) return;
    const float4* row = (const float4*)(feats + (size_t)warp * D);
    float ss = 0.f;
#pragma unroll
    for (int k = 0; k < 4; k++) {
        float4 v = row[lane + 32 * k];
        ss += v.x * v.x + v.y * v.y + v.z * v.z + v.w * v.w;
    }
#pragma unroll
    for (int o = 16; o; o >>= 1) ss += __shfl_xor_sync(0xffffffffu, ss, o);
    if (lane == 0) g_invn[warp] = 1.0f / fmaxf(sqrtf(ss), 1e-8f);
}

// ---------------- shared helpers ----------------
__device__ __forceinline__ void stage_rows(const float* __restrict__ F,
                                           const int* idx, int n,
                                           float4* stage, const float4** rowp) {
    int nst = n < SCAP ? n : SCAP;
    int tot = nst * D4;
    for (int q = threadIdx.x; q < tot; q += blockDim.x) {
        int r = q >> 7, c = q & 127;
        stage[q] = ((const float4*)(F + (size_t)idx[r] * D))[c];
    }
    for (int r = threadIdx.x; r < n; r += blockDim.x)
        rowp[r] = (r < nst) ? (const float4*)(stage + r * D4)
                            : (const float4*)(F + (size_t)idx[r] * D);
}

// warp-per-pair cosine of strict lower triangle; diag set to 1.0f
// (ref diag = clip(~1.0, max 1-1e-8) which rounds to 1.0f in fp32; diffs O(1ulp))
__device__ __forceinline__ void build_sims(const float4* const* rowp,
                                           const float* sinv, int n, float* sim) {
    const int w = threadIdx.x >> 5, lane = threadIdx.x & 31, nw = blockDim.x >> 5;
    const int npair = n * (n - 1) / 2;
    for (int p = w; p < npair; p += nw) {
        int i = (int)((1.0f + sqrtf(8.0f * (float)p + 1.0f)) * 0.5f);
        while (i * (i - 1) / 2 > p) i--;
        while ((i + 1) * i / 2 <= p) i++;
        int j = p - i * (i - 1) / 2;
        const float4* a = rowp[i];
        const float4* b = rowp[j];
        float dot = 0.f;
#pragma unroll
        for (int k = 0; k < 4; k++) {
            float4 x = a[lane + 32 * k];
            float4 y = b[lane + 32 * k];
            dot += x.x * y.x + x.y * y.y + x.z * y.z + x.w * y.w;
        }
#pragma unroll
        for (int o = 16; o; o >>= 1) dot += __shfl_xor_sync(0xffffffffu, dot, o);
        if (lane == 0) {
            float s = dot * sinv[i] * sinv[j];
            s = fminf(fmaxf(s, -1.0f), 1.0f);   // fp32 clip bounds round to +/-1
            sim[i * MAXN + j] = s;
            sim[j * MAXN + i] = s;
        }
    }
    for (int i = threadIdx.x; i < n; i += blockDim.x) sim[i * MAXN + i] = 1.0f;
}

// top-5 with jax.lax.top_k tie-break (equal values -> lower index)
__device__ __forceinline__ void top5_row(const float* row, int n, int self, int* ch) {
#pragma unroll
    for (int t = 0; t < KTOP; t++) {
        float bv = 0.f;   // only strictly-positive sims are candidates
        int   bj = -1;
        for (int j = 0; j < n; j++) {
            if (j == self) continue;
            bool used = false;
            for (int u = 0; u < t; u++) if (ch[u] == j) used = true;
            if (used) continue;
            float v = row[j];
            if (v > bv) { bv = v; bj = j; }
        }
        ch[t] = bj;
    }
}

// ---------------- kernel A: layer-7 knn on full class -> subset ----------------
__global__ __launch_bounds__(256) void subset_kernel(const float* __restrict__ feats,
                                                     const int*   __restrict__ labels) {
    extern __shared__ float4 stage[];
    __shared__ int           midx[MAXN];
    __shared__ float         sinv[MAXN];
    __shared__ const float4* rowp[MAXN];
    __shared__ float         sim[MAXN * MAXN];
    __shared__ unsigned char keep[MAXN], insub[MAXN];
    __shared__ int           scan[256];
    __shared__ int           sn;

    const int cls = blockIdx.x, tid = threadIdx.x, is64 = g_is64;

    int loc[8]; int c = 0;
#pragma unroll
    for (int k = 0; k < 8; k++) {
        int gi = tid * 8 + k;
        int lb = is64 ? labels[2 * gi] : labels[gi];
        if (lb == cls) loc[c++] = gi;
    }
    scan[tid] = c;
    __syncthreads();
    for (int off = 1; off < 256; off <<= 1) {
        int v = (tid >= off) ? scan[tid - off] : 0;
        __syncthreads();
        scan[tid] += v;
        __syncthreads();
    }
    int start = scan[tid] - c;
    for (int k = 0; k < c; k++) {
        int pos = start + k;
        if (pos < MAXN) midx[pos] = loc[k];
    }
    if (tid == 255) sn = scan[255] < MAXN ? scan[255] : MAXN;
    __syncthreads();
    const int n = sn;
    if (n == 0) { if (tid == 0) g_n2[cls] = 0; return; }

    const float* F = feats + (size_t)(LYR - 1) * NS * D;
    for (int r = tid; r < n; r += 256) sinv[r] = g_invn[(LYR - 1) * NS + midx[r]];
    stage_rows(F, midx, n, stage, rowp);
    __syncthreads();
    build_sims(rowp, sinv, n, sim);
    __syncthreads();

    if (tid < n) {
        insub[tid] = 0;
        const float* row = sim + tid * MAXN;
        int cand = 0;
        for (int j = 0; j < n; j++)
            if (j != tid && row[j] > 0.f) cand++;
        keep[tid] = (cand >= KTOP) ? 1 : 0;
    }
    __syncthreads();
    if (tid < n && keep[tid]) {
        const float* row = sim + tid * MAXN;
        int ch[KTOP];
        top5_row(row, n, tid, ch);
#pragma unroll
        for (int t = 0; t < KTOP; t++) {
            int j = ch[t];
            if (j >= 0 && keep[j]) { insub[tid] = 1; insub[j] = 1; }  // benign race
        }
    }
    __syncthreads();
    if (tid == 0) {
        int m = 0;
        for (int i = 0; i < n; i++)
            if (insub[i]) g_sub[cls * MAXN + m++] = midx[i];
        g_n2[cls] = m;
    }
}

// ---------------- kernel B: per (class,layer) sims + knn mask + ema ----------------
__global__ __launch_bounds__(256) void layer_kernel(const float* __restrict__ feats) {
    extern __shared__ float4 stage[];
    __shared__ int           sidx[MAXN];
    __shared__ float         sinv[MAXN];
    __shared__ const float4* rowp[MAXN];
    __shared__ float         sim[MAXN * MAXN];
    __shared__ unsigned char msk[MAXN * MAXN];
    __shared__ float         ema[MAXN];
    __shared__ unsigned char keep[MAXN];

    const int cls = blockIdx.x & (NCLS - 1);
    const int l   = blockIdx.x >> 7;
    const int tid = threadIdx.x;
    const int n2  = g_n2[cls];
    if (n2 == 0) return;

    for (int r = tid; r < n2; r += 256) {
        int gi = g_sub[cls * MAXN + r];
        sidx[r] = gi;
        sinv[r] = g_invn[l * NS + gi];
    }
    __syncthreads();
    const float* F = feats + (size_t)l * NS * D;
    stage_rows(F, sidx, n2, stage, rowp);
    for (int p = tid; p < n2 * MAXN; p += 256) msk[p] = 0;
    __syncthreads();
    build_sims(rowp, sinv, n2, sim);
    __syncthreads();

    if (tid < n2) {
        const float* row = sim + tid * MAXN;
        float rs = 0.f;
        int dg = 0, cand = 0;
        for (int j = 0; j < n2; j++) {
            float v = row[j];
            if (v > 0.f) { rs += v; dg++; if (j != tid) cand++; }
        }
        float degf = (float)(dg > 0 ? dg : 1);
        float sc   = 1.0f / (1.0f + expf(-rs / degf));
        ema[tid]  = 0.45f + 0.1f * sc;           // MOM*0.5 + (1-MOM)*score
        keep[tid] = (cand >= KTOP) ? 1 : 0;
    }
    __syncthreads();
    if (tid < n2 && keep[tid]) {
        const float* row = sim + tid * MAXN;
        int ch[KTOP];
        top5_row(row, n2, tid, ch);
#pragma unroll
        for (int t = 0; t < KTOP; t++) {
            int j = ch[t];
            if (j >= 0 && keep[j]) msk[tid * MAXN + j] = 1;
        }
    }
    __syncthreads();

    size_t gb = (size_t)(l * NCLS + cls) * MAXN * MAXN;
    for (int p = tid; p < n2 * n2; p += 256) {
        int i = p / n2, j = p % n2;
        int o = i * MAXN + j;
        g_sim[gb + o] = sim[o];
        g_msk[gb + o] = (unsigned char)(msk[o] | msk[j * MAXN + i]);  // symmetrized
    }
    if (tid < n2) g_w[(l * NCLS + cls) * MAXN + tid] = ema[tid];
}

// ---------------- kernel C: per (class, layer-pair) accumulation ----------------
__global__ __launch_bounds__(256) void accum_kernel() {
    const int cls = blockIdx.x & (NCLS - 1);
    const int t   = blockIdx.x >> 7;     // 0..6
    const int tid = threadIdx.x;
    const int n2  = g_n2[cls];
    if (n2 == 0) return;

    const size_t bp = (size_t)(t * NCLS + cls) * MAXN * MAXN;
    const size_t bc = (size_t)((t + 1) * NCLS + cls) * MAXN * MAXN;
    const float* wp = g_w + (size_t)(t * NCLS + cls) * MAXN;

    float pnum = 0.f, pden = 0.f;
    for (int p = tid; p < n2 * n2; p += 256) {
        int i = p / n2, j = p % n2;
        if (i == j) continue;
        int o  = i * MAXN + j;
        int ml = g_msk[bp + o];
        int mc = g_msk[bc + o];
        if (ml | mc) {
            float w  = wp[i] * wp[j];
            float al = ml ? g_sim[bp + o] : 0.f;   // A = sim * M (chosen sims > 0)
            float ac = mc ? g_sim[bc + o] : 0.f;
            float d  = ac - al;
            pnum += d * d * w;
            pden += w;
        }
    }
#pragma unroll
    for (int o = 16; o; o >>= 1) {
        pnum += __shfl_xor_sync(0xffffffffu, pnum, o);
        pden += __shfl_xor_sync(0xffffffffu, pden, o);
    }
    if ((tid & 31) == 0 && (pnum != 0.f || pden != 0.f)) {
        atomicAdd(&g_num[t], pnum);
        atomicAdd(&g_den[t], pden);
    }
}

// ---------------- kernel D: combine ----------------
__global__ void final_kernel(float* out) {
    if (blockIdx.x == 0 && threadIdx.x == 0) {
        float raw = 0.f;
        for (int t = 0; t < LYR - 1; t++)
            if (g_den[t] > 0.f)                   // M_eff.sum() > 0 <=> any edge
                raw += g_num[t] / fmaxf(g_den[t], 1e-8f);
        out[0] = 16.0f * (raw / 7.0f);            // LAMBDA_ALIGN_K * raw / (L-1)
    }
}

extern "C" void kernel_launch(void* const* d_in, const int* in_sizes, int n_in,
                              void* d_out, int out_size) {
    const float* feats  = (const float*)d_in[0];
    const int*   labels = (const int*)d_in[1];   // int32 or int64; detected at runtime
    const int*   sids   = (const int*)d_in[2];
    float*       out    = (float*)d_out;

    const int DYN = SCAP * D * (int)sizeof(float);  // 64 KB staged rows
    cudaFuncSetAttribute(subset_kernel, cudaFuncAttributeMaxDynamicSharedMemorySize, DYN);
    cudaFuncSetAttribute(layer_kernel,  cudaFuncAttributeMaxDynamicSharedMemorySize, DYN);

    prep_kernel<<<2048, 256>>>(feats, sids);
    subset_kernel<<<NCLS, 256, DYN>>>(feats, labels);
    layer_kernel<<<LYR * NCLS, 256, DYN>>>(feats);
    accum_kernel<<<(LYR - 1) * NCLS, 256>>>();
    final_kernel<<<1, 32>>>(out);
}

// round 3
// speedup vs baseline: 3.9450x; 1.2654x over previous
#include <cuda_runtime.h>
#include <math.h>

#define NS    2048
#define D     512
#define D4    128
#define LYR   8
#define NT    7            // layer pairs
#define NCLS  128
#define MAXN  64
#define SCAP_SUB 40        // rows staged in shared (subset kernel)
#define SCAP_LAY 26        // rows staged in shared (layer kernel)
#define KTOP  5

// ---------------- device scratch (no allocations allowed) ----------------
__device__ int           g_sub[NCLS * MAXN];
__device__ int           g_n2[NCLS];
__device__ float         g_sim[(size_t)LYR * NCLS * MAXN * MAXN];   // 16.8 MB
__device__ unsigned char g_msk[(size_t)LYR * NCLS * MAXN * MAXN];   // 4.2 MB
__device__ float         g_w[LYR * NCLS * MAXN];
__device__ float         g_pnum[NT * NCLS];
__device__ float         g_pden[NT * NCLS];
__device__ int           g_ctr = 0;

// ---------------- helpers ----------------
// stage up to `nst` rows into shared; pointer table covers fallback rows in global
__device__ __forceinline__ void stage_rows(const float* __restrict__ F,
                                           const int* idx, int n, int nst,
                                           float4* stage, const float4** rowp) {
    if (nst > n) nst = n;
    int tot = nst * D4;
    for (int q = threadIdx.x; q < tot; q += blockDim.x) {
        int r = q >> 7, c = q & 127;
        stage[q] = ((const float4*)(F + (size_t)idx[r] * D))[c];
    }
    for (int r = threadIdx.x; r < n; r += blockDim.x)
        rowp[r] = (r < nst) ? (const float4*)(stage + r * D4)
                            : (const float4*)(F + (size_t)idx[r] * D);
}

// inverse norms from the (staged) rows; same reduction tree as reference path
__device__ __forceinline__ void compute_invn(const float4* const* rowp, int n, float* sinv) {
    const int w = threadIdx.x >> 5, lane = threadIdx.x & 31, nw = blockDim.x >> 5;
    for (int r = w; r < n; r += nw) {
        const float4* a = rowp[r];
        float ss = 0.f;
#pragma unroll
        for (int k = 0; k < 4; k++) {
            float4 v = a[lane + 32 * k];
            ss += v.x * v.x + v.y * v.y + v.z * v.z + v.w * v.w;
        }
#pragma unroll
        for (int o = 16; o; o >>= 1) ss += __shfl_xor_sync(0xffffffffu, ss, o);
        if (lane == 0) sinv[r] = 1.0f / fmaxf(sqrtf(ss), 1e-8f);
    }
}

// cosine of strict lower triangle; 4 pairs per warp (8 lanes per dot, lane
// quarters align with LDS.128 phases -> conflict-free). diag set to 1.0f
// (ref diag = clip(~1, 1-1e-8) which rounds to exactly 1.0f in fp32).
__device__ __forceinline__ void build_sims(const float4* const* rowp,
                                           const float* sinv, int n, float* sim) {
    const int w = threadIdx.x >> 5, lane = threadIdx.x & 31, nw = blockDim.x >> 5;
    const int grp = lane >> 3, l8 = lane & 7;
    const int npair = n * (n - 1) / 2;
    for (int pb = w * 4; pb < npair; pb += nw * 4) {
        int p  = pb + grp;
        int pc = (p < npair) ? p : npair - 1;
        int i = (int)((1.0f + sqrtf(8.0f * (float)pc + 1.0f)) * 0.5f);
        while (i * (i - 1) / 2 > pc) i--;
        while ((i + 1) * i / 2 <= pc) i++;
        int j = pc - i * (i - 1) / 2;
        const float4* a = rowp[i];
        const float4* b = rowp[j];
        float dot = 0.f;
#pragma unroll
        for (int k = 0; k < 16; k++) {
            float4 x = a[l8 + 8 * k];
            float4 y = b[l8 + 8 * k];
            dot += x.x * y.x + x.y * y.y + x.z * y.z + x.w * y.w;
        }
#pragma unroll
        for (int o = 4; o; o >>= 1) dot += __shfl_xor_sync(0xffffffffu, dot, o);
        if (l8 == 0 && p < npair) {
            float s = dot * sinv[i] * sinv[j];
            s = fminf(fmaxf(s, -1.0f), 1.0f);   // fp32 clip bounds round to +/-1
            sim[i * MAXN + j] = s;
            sim[j * MAXN + i] = s;
        }
    }
    for (int i = threadIdx.x; i < n; i += blockDim.x) sim[i * MAXN + i] = 1.0f;
}

// top-5 with jax.lax.top_k tie-break (equal values -> lower index)
__device__ __forceinline__ void top5_row(const float* row, int n, int self, int* ch) {
#pragma unroll
    for (int t = 0; t < KTOP; t++) {
        float bv = 0.f;   // only strictly-positive sims are candidates
        int   bj = -1;
        for (int j = 0; j < n; j++) {
            if (j == self) continue;
            bool used = false;
            for (int u = 0; u < t; u++) if (ch[u] == j) used = true;
            if (used) continue;
            float v = row[j];
            if (v > bv) { bv = v; bj = j; }
        }
        ch[t] = bj;
    }
}

// knn mask + ema on an n2 x n2 sim block, then store per-(layer,class) results
__device__ __forceinline__ void knn_phase_and_store(const float* sim, int n2, int l, int cls,
                                                    unsigned char* msk, float* ema,
                                                    unsigned char* keep) {
    const int tid = threadIdx.x;
    for (int p = tid; p < n2 * MAXN; p += blockDim.x) msk[p] = 0;
    __syncthreads();
    if (tid < n2) {
        const float* row = sim + tid * MAXN;
        float rs = 0.f;
        int dg = 0, cand = 0;
        for (int j = 0; j < n2; j++) {
            float v = row[j];
            if (v > 0.f) { rs += v; dg++; if (j != tid) cand++; }
        }
        float degf = (float)(dg > 0 ? dg : 1);
        float sc   = 1.0f / (1.0f + expf(-rs / degf));
        ema[tid]  = 0.45f + 0.1f * sc;            // MOM*0.5 + (1-MOM)*score
        keep[tid] = (cand >= KTOP) ? 1 : 0;
    }
    __syncthreads();
    if (tid < n2 && keep[tid]) {
        const float* row = sim + tid * MAXN;
        int ch[KTOP];
        top5_row(row, n2, tid, ch);
#pragma unroll
        for (int t = 0; t < KTOP; t++) {
            int j = ch[t];
            if (j >= 0 && keep[j]) msk[tid * MAXN + j] = 1;
        }
    }
    __syncthreads();
    size_t gb = (size_t)(l * NCLS + cls) * MAXN * MAXN;
    for (int p = tid; p < n2 * n2; p += blockDim.x) {
        int i = p / n2, j = p % n2;
        int o = i * MAXN + j;
        g_sim[gb + o] = sim[o];
        g_msk[gb + o] = (unsigned char)(msk[o] | msk[j * MAXN + i]);  // symmetrized
    }
    if (tid < n2) g_w[(l * NCLS + cls) * MAXN + tid] = ema[tid];
}

// ---------------- kernel A: layer-7 knn on full class -> subset + layer-7 outputs --
__global__ __launch_bounds__(256) void subset_kernel(const float* __restrict__ feats,
                                                     const int*   __restrict__ labels,
                                                     const int*   __restrict__ sids32) {
    extern __shared__ float4 stage[];
    __shared__ int           midx[MAXN];
    __shared__ float         sinv[MAXN];
    __shared__ const float4* rowp[MAXN];
    __shared__ float         sim[MAXN * MAXN];
    __shared__ float         sim2[MAXN * MAXN];
    __shared__ unsigned char msk[MAXN * MAXN];
    __shared__ float         ema[MAXN];
    __shared__ unsigned char keep[MAXN], insub[MAXN];
    __shared__ int           sm[MAXN];
    __shared__ int           scan[256];
    __shared__ int           sn, sn2;

    const int cls = blockIdx.x, tid = threadIdx.x;
    // sample_ids = arange. int64 -> int32 words [0,0,1,0,...]; word[2]==1 iff int64
    const int is64 = (sids32[2] == 1) ? 1 : 0;

    int loc[8]; int c = 0;
#pragma unroll
    for (int k = 0; k < 8; k++) {
        int gi = tid * 8 + k;
        int lb = is64 ? labels[2 * gi] : labels[gi];
        if (lb == cls) loc[c++] = gi;
    }
    scan[tid] = c;
    __syncthreads();
    for (int off = 1; off < 256; off <<= 1) {
        int v = (tid >= off) ? scan[tid - off] : 0;
        __syncthreads();
        scan[tid] += v;
        __syncthreads();
    }
    int start = scan[tid] - c;
    for (int k = 0; k < c; k++) {
        int pos = start + k;
        if (pos < MAXN) midx[pos] = loc[k];
    }
    if (tid == 255) sn = scan[255] < MAXN ? scan[255] : MAXN;
    __syncthreads();
    const int n = sn;
    if (n == 0) { if (tid == 0) g_n2[cls] = 0; return; }

    const float* F = feats + (size_t)(LYR - 1) * NS * D;
    stage_rows(F, midx, n, SCAP_SUB, stage, rowp);
    __syncthreads();
    compute_invn(rowp, n, sinv);
    __syncthreads();
    build_sims(rowp, sinv, n, sim);
    __syncthreads();

    if (tid < n) {
        insub[tid] = 0;
        const float* row = sim + tid * MAXN;
        int cand = 0;
        for (int j = 0; j < n; j++)
            if (j != tid && row[j] > 0.f) cand++;
        keep[tid] = (cand >= KTOP) ? 1 : 0;
    }
    __syncthreads();
    if (tid < n && keep[tid]) {
        const float* row = sim + tid * MAXN;
        int ch[KTOP];
        top5_row(row, n, tid, ch);
#pragma unroll
        for (int t = 0; t < KTOP; t++) {
            int j = ch[t];
            if (j >= 0 && keep[j]) { insub[tid] = 1; insub[j] = 1; }  // benign race
        }
    }
    __syncthreads();
    if (tid == 0) {
        int m = 0;
        for (int i = 0; i < n; i++)
            if (insub[i]) { sm[m] = i; g_sub[cls * MAXN + m] = midx[i]; m++; }
        sn2 = m;
        g_n2[cls] = m;
    }
    __syncthreads();
    const int n2 = sn2;
    if (n2 == 0) return;

    // layer-7 outputs directly from the full-class sim submatrix (no recompute)
    for (int p = tid; p < n2 * n2; p += 256) {
        int a = p / n2, b = p % n2;
        sim2[a * MAXN + b] = sim[sm[a] * MAXN + sm[b]];
    }
    __syncthreads();
    knn_phase_and_store(sim2, n2, LYR - 1, cls, msk, ema, keep);
}

// ---------------- kernel B: per (class, layer 0..6) sims + knn + ema ----------------
__global__ __launch_bounds__(256) void layer_kernel(const float* __restrict__ feats) {
    extern __shared__ float4 stage[];
    __shared__ int           sidx[MAXN];
    __shared__ float         sinv[MAXN];
    __shared__ const float4* rowp[MAXN];
    __shared__ float         sim[MAXN * MAXN];
    __shared__ unsigned char msk[MAXN * MAXN];
    __shared__ float         ema[MAXN];
    __shared__ unsigned char keep[MAXN];

    const int cls = blockIdx.x & (NCLS - 1);
    const int l   = blockIdx.x >> 7;        // 0..6
    const int tid = threadIdx.x;
    const int n2  = g_n2[cls];
    if (n2 == 0) return;

    for (int r = tid; r < n2; r += 256) sidx[r] = g_sub[cls * MAXN + r];
    __syncthreads();
    const float* F = feats + (size_t)l * NS * D;
    stage_rows(F, sidx, n2, SCAP_LAY, stage, rowp);
    __syncthreads();
    compute_invn(rowp, n2, sinv);
    __syncthreads();
    build_sims(rowp, sinv, n2, sim);
    __syncthreads();
    knn_phase_and_store(sim, n2, l, cls, msk, ema, keep);
}

// ---------------- kernel C: accumulation (no atomics) + fused final combine --------
__global__ __launch_bounds__(128) void accum_final(float* __restrict__ out) {
    const int blk = blockIdx.x;              // 0..895
    const int cls = blk & (NCLS - 1);
    const int t   = blk >> 7;                // 0..6
    const int tid = threadIdx.x;
    const int n2  = g_n2[cls];

    float pnum = 0.f, pden = 0.f;
    if (n2 > 1) {
        const size_t bp = (size_t)(t * NCLS + cls) * MAXN * MAXN;
        const size_t bc = (size_t)((t + 1) * NCLS + cls) * MAXN * MAXN;
        const float* wp = g_w + (size_t)(t * NCLS + cls) * MAXN;
        for (int p = tid; p < n2 * n2; p += 128) {
            int i = p / n2, j = p % n2;
            if (i == j) continue;
            int o  = i * MAXN + j;
            int ml = g_msk[bp + o];
            int mc = g_msk[bc + o];
            if (ml | mc) {
                float w  = wp[i] * wp[j];
                float al = ml ? g_sim[bp + o] : 0.f;   // A = sim * M (masked sims > 0)
                float ac = mc ? g_sim[bc + o] : 0.f;
                float d  = ac - al;
                pnum += d * d * w;
                pden += w;
            }
        }
    }
    // block reduce (4 warps)
    __shared__ float swn[4], swd[4];
    __shared__ int   done;
#pragma unroll
    for (int o = 16; o; o >>= 1) {
        pnum += __shfl_xor_sync(0xffffffffu, pnum, o);
        pden += __shfl_xor_sync(0xffffffffu, pden, o);
    }
    if ((tid & 31) == 0) { swn[tid >> 5] = pnum; swd[tid >> 5] = pden; }
    __syncthreads();
    if (tid == 0) {
        float tn = swn[0] + swn[1] + swn[2] + swn[3];
        float td = swd[0] + swd[1] + swd[2] + swd[3];
        g_pnum[blk] = tn;
        g_pden[blk] = td;
        __threadfence();
        int old = atomicAdd(&g_ctr, 1);
        done = (old == NT * NCLS - 1) ? 1 : 0;
    }
    __syncthreads();
    if (!done) return;

    // last block: deterministic combine of all 896 partials
    __shared__ float red[128];
    __shared__ float tnum[NT], tden[NT];
    for (int t2 = 0; t2 < NT; t2++) {
        red[tid] = g_pnum[t2 * NCLS + tid];
        __syncthreads();
        for (int s = 64; s; s >>= 1) { if (tid < s) red[tid] += red[tid + s]; __syncthreads(); }
        if (tid == 0) tnum[t2] = red[0];
        __syncthreads();
        red[tid] = g_pden[t2 * NCLS + tid];
        __syncthreads();
        for (int s = 64; s; s >>= 1) { if (tid < s) red[tid] += red[tid + s]; __syncthreads(); }
        if (tid == 0) tden[t2] = red[0];
        __syncthreads();
    }
    if (tid == 0) {
        float raw = 0.f;
        for (int t2 = 0; t2 < NT; t2++)
            if (tden[t2] > 0.f)                       // M_eff.sum() > 0 <=> any edge
                raw += tnum[t2] / fmaxf(tden[t2], 1e-8f);
        out[0] = 16.0f * (raw / 7.0f);                // LAMBDA_ALIGN_K * raw / (L-1)
        g_ctr = 0;                                    // reset for next graph replay
    }
}

extern "C" void kernel_launch(void* const* d_in, const int* in_sizes, int n_in,
                              void* d_out, int out_size) {
    const float* feats  = (const float*)d_in[0];
    const int*   labels = (const int*)d_in[1];   // int32 or int64; detected at runtime
    const int*   sids   = (const int*)d_in[2];
    float*       out    = (float*)d_out;

    const int DYN_SUB = SCAP_SUB * D * (int)sizeof(float);  // 80 KB
    const int DYN_LAY = SCAP_LAY * D * (int)sizeof(float);  // 52 KB
    cudaFuncSetAttribute(subset_kernel, cudaFuncAttributeMaxDynamicSharedMemorySize, DYN_SUB);
    cudaFuncSetAttribute(layer_kernel,  cudaFuncAttributeMaxDynamicSharedMemorySize, DYN_LAY);

    subset_kernel<<<NCLS, 256, DYN_SUB>>>(feats, labels, sids);
    layer_kernel<<<NT * NCLS, 256, DYN_LAY>>>(feats);
    accum_final<<<NT * NCLS, 128>>>(out);
}

// round 4
// speedup vs baseline: 4.7560x; 1.2056x over previous
#include <cuda_runtime.h>
#include <math.h>

#define NS    2048
#define D     512
#define D4    128
#define DPAD  129          // padded float4 row stride in stage (kills bank conflicts)
#define LYR   8
#define NT    7            // layer pairs
#define NCLS  128
#define MAXN  64
#define SCAP  27           // rows staged in shared (27*129*16B = 55.7KB -> 4 CTAs/SM)
#define KTOP  5

// ---------------- device scratch (no allocations allowed) ----------------
__device__ int           g_mem[NCLS * MAXN];    // full-class member lists
__device__ int           g_n[NCLS];
__device__ int           g_smap[NCLS * MAXN];   // subset -> member-position map
__device__ int           g_n2[NCLS];
__device__ float         g_sim[(size_t)LYR * NCLS * MAXN * MAXN];   // 16.8 MB, full-class sims
__device__ unsigned char g_msk[(size_t)LYR * NCLS * MAXN * MAXN];   // subset-coord masks
__device__ float         g_w[LYR * NCLS * MAXN];
__device__ float         g_pnum[NT * NCLS];
__device__ float         g_pden[NT * NCLS];
__device__ int           g_ctr = 0;

// ---------------- kernel 1: per (layer,class) full-class cosine blocks -------------
__global__ __launch_bounds__(256) void sims_kernel(const float* __restrict__ feats,
                                                   const int*   __restrict__ labels,
                                                   const int*   __restrict__ sids32) {
    extern __shared__ float4 stage[];            // SCAP rows, DPAD float4 stride
    __shared__ int           midx[MAXN];
    __shared__ float         sinv[MAXN];
    __shared__ const float4* rowp[MAXN];
    __shared__ int           scan[256];
    __shared__ int           sn;

    const int cls = blockIdx.x & (NCLS - 1);
    const int l   = blockIdx.x >> 7;
    const int tid = threadIdx.x;
    // sample_ids = arange. int64 -> int32 words [0,0,1,0,...]; word[2]==1 iff int64
    const int is64 = (sids32[2] == 1) ? 1 : 0;

    // ---- member list (each CTA derives it independently; labels are L2-hot) ----
    int loc[8]; int c = 0;
#pragma unroll
    for (int k = 0; k < 8; k++) {
        int gi = tid * 8 + k;
        int lb = is64 ? labels[2 * gi] : labels[gi];
        if (lb == cls) loc[c++] = gi;
    }
    scan[tid] = c;
    __syncthreads();
    for (int off = 1; off < 256; off <<= 1) {
        int v = (tid >= off) ? scan[tid - off] : 0;
        __syncthreads();
        scan[tid] += v;
        __syncthreads();
    }
    int start = scan[tid] - c;
    for (int k = 0; k < c; k++) {
        int pos = start + k;
        if (pos < MAXN) midx[pos] = loc[k];
    }
    if (tid == 255) sn = scan[255] < MAXN ? scan[255] : MAXN;
    __syncthreads();
    const int n = sn;
    if (l == 0) {                         // one CTA per class publishes the list
        if (tid == 0) g_n[cls] = n;
        for (int r = tid; r < n; r += 256) g_mem[cls * MAXN + r] = midx[r];
    }
    if (n == 0) return;

    // ---- stage rows (padded) ----
    const float* F = feats + (size_t)l * NS * D;
    int nst = n < SCAP ? n : SCAP;
    for (int q = tid; q < nst * D4; q += 256) {
        int r = q >> 7, cc = q & 127;
        stage[r * DPAD + cc] = ((const float4*)(F + (size_t)midx[r] * D))[cc];
    }
    for (int r = tid; r < n; r += 256)
        rowp[r] = (r < nst) ? (const float4*)(stage + r * DPAD)
                            : (const float4*)(F + (size_t)midx[r] * D);
    __syncthreads();

    // ---- inverse norms (warp per row; same tree as reference path) ----
    {
        const int w = tid >> 5, lane = tid & 31;
        for (int r = w; r < n; r += 8) {
            const float4* a = rowp[r];
            float ss = 0.f;
#pragma unroll
            for (int k = 0; k < 4; k++) {
                float4 v = a[lane + 32 * k];
                ss += v.x * v.x + v.y * v.y + v.z * v.z + v.w * v.w;
            }
#pragma unroll
            for (int o = 16; o; o >>= 1) ss += __shfl_xor_sync(0xffffffffu, ss, o);
            if (lane == 0) sinv[r] = 1.0f / fmaxf(sqrtf(ss), 1e-8f);
        }
    }
    __syncthreads();

    // ---- sims: 4 pairs per warp (8 lanes per dot), write straight to global ----
    float* gsim = g_sim + (size_t)(l * NCLS + cls) * MAXN * MAXN;
    {
        const int w = tid >> 5, lane = tid & 31;
        const int grp = lane >> 3, l8 = lane & 7;
        const int npair = n * (n - 1) / 2;
        for (int pb = w * 4; pb < npair; pb += 32) {
            int p  = pb + grp;
            int pc = (p < npair) ? p : npair - 1;
            int i = (int)((1.0f + sqrtf(8.0f * (float)pc + 1.0f)) * 0.5f);
            while (i * (i - 1) / 2 > pc) i--;
            while ((i + 1) * i / 2 <= pc) i++;
            int j = pc - i * (i - 1) / 2;
            const float4* a = rowp[i];
            const float4* b = rowp[j];
            float dot = 0.f;
#pragma unroll
            for (int k = 0; k < 16; k++) {
                float4 x = a[l8 + 8 * k];
                float4 y = b[l8 + 8 * k];
                dot += x.x * y.x + x.y * y.y + x.z * y.z + x.w * y.w;
            }
#pragma unroll
            for (int o = 4; o; o >>= 1) dot += __shfl_xor_sync(0xffffffffu, dot, o);
            if (l8 == 0 && p < npair) {
                float s = dot * sinv[i] * sinv[j];
                s = fminf(fmaxf(s, -1.0f), 1.0f);   // fp32 clip bounds round to +/-1
                gsim[i * MAXN + j] = s;
                gsim[j * MAXN + i] = s;
            }
        }
        // diag = clip(~1, 1-1e-8) -> exactly 1.0f in fp32
        for (int i = tid; i < n; i += 256) gsim[i * MAXN + i] = 1.0f;
    }
}

// top-5 with jax.lax.top_k tie-break (equal values -> lower index)
__device__ __forceinline__ void top5_row(const float* row, int n, int self, int* ch) {
#pragma unroll
    for (int t = 0; t < KTOP; t++) {
        float bv = 0.f;   // only strictly-positive sims are candidates
        int   bj = -1;
        for (int j = 0; j < n; j++) {
            if (j == self) continue;
            bool used = false;
            for (int u = 0; u < t; u++) if (ch[u] == j) used = true;
            if (used) continue;
            float v = row[j];
            if (v > bv) { bv = v; bj = j; }
        }
        ch[t] = bj;
    }
}

// ---------------- kernel 2: layer-7 knn on full class -> subset map ----------------
__global__ __launch_bounds__(256) void subset_kernel() {
    __shared__ float         sim[MAXN * MAXN];
    __shared__ unsigned char keep[MAXN], insub[MAXN];

    const int cls = blockIdx.x, tid = threadIdx.x;
    const int n = g_n[cls];
    if (n == 0) { if (tid == 0) g_n2[cls] = 0; return; }

    const float* gsim = g_sim + (size_t)((LYR - 1) * NCLS + cls) * MAXN * MAXN;
    for (int p = tid; p < n * MAXN; p += 256) sim[p] = gsim[p];
    __syncthreads();

    if (tid < n) {
        insub[tid] = 0;
        const float* row = sim + tid * MAXN;
        int cand = 0;
        for (int j = 0; j < n; j++)
            if (j != tid && row[j] > 0.f) cand++;
        keep[tid] = (cand >= KTOP) ? 1 : 0;
    }
    __syncthreads();
    if (tid < n && keep[tid]) {
        const float* row = sim + tid * MAXN;
        int ch[KTOP];
        top5_row(row, n, tid, ch);
#pragma unroll
        for (int t = 0; t < KTOP; t++) {
            int j = ch[t];
            if (j >= 0 && keep[j]) { insub[tid] = 1; insub[j] = 1; }  // benign race
        }
    }
    __syncthreads();
    if (tid == 0) {
        int m = 0;
        for (int i = 0; i < n; i++)
            if (insub[i]) g_smap[cls * MAXN + m++] = i;   // member-position indices
        g_n2[cls] = m;
    }
}

// ---------------- kernel 3: per (class,layer) knn mask + ema on the subset ---------
__global__ __launch_bounds__(256) void knn_kernel() {
    __shared__ int           smap[MAXN];
    __shared__ float         sim[MAXN * MAXN];
    __shared__ unsigned char msk[MAXN * MAXN];
    __shared__ unsigned char keep[MAXN];

    const int cls = blockIdx.x & (NCLS - 1);
    const int l   = blockIdx.x >> 7;
    const int tid = threadIdx.x;
    const int n2  = g_n2[cls];
    if (n2 == 0) return;

    for (int r = tid; r < n2; r += 256) smap[r] = g_smap[cls * MAXN + r];
    __syncthreads();

    const float* gsim = g_sim + (size_t)(l * NCLS + cls) * MAXN * MAXN;
    for (int p = tid; p < n2 * n2; p += 256) {
        int i = p / n2, j = p % n2;
        sim[i * MAXN + j] = gsim[smap[i] * MAXN + smap[j]];
    }
    for (int p = tid; p < n2 * MAXN; p += 256) msk[p] = 0;
    __syncthreads();

    float emaval = 0.f;
    if (tid < n2) {
        const float* row = sim + tid * MAXN;
        float rs = 0.f;
        int dg = 0, cand = 0;
        for (int j = 0; j < n2; j++) {
            float v = row[j];
            if (v > 0.f) { rs += v; dg++; if (j != tid) cand++; }
        }
        float degf = (float)(dg > 0 ? dg : 1);
        float sc   = 1.0f / (1.0f + expf(-rs / degf));
        emaval    = 0.45f + 0.1f * sc;            // MOM*0.5 + (1-MOM)*score
        keep[tid] = (cand >= KTOP) ? 1 : 0;
    }
    __syncthreads();
    if (tid < n2 && keep[tid]) {
        const float* row = sim + tid * MAXN;
        int ch[KTOP];
        top5_row(row, n2, tid, ch);
#pragma unroll
        for (int t = 0; t < KTOP; t++) {
            int j = ch[t];
            if (j >= 0 && keep[j]) msk[tid * MAXN + j] = 1;
        }
    }
    __syncthreads();

    unsigned char* gm = g_msk + (size_t)(l * NCLS + cls) * MAXN * MAXN;
    for (int p = tid; p < n2 * n2; p += 256) {
        int i = p / n2, j = p % n2;
        gm[i * MAXN + j] = (unsigned char)(msk[i * MAXN + j] | msk[j * MAXN + i]); // symm
    }
    if (tid < n2) g_w[(l * NCLS + cls) * MAXN + tid] = emaval;
}

// ---------------- kernel 4: accumulation (no atomics) + fused final combine --------
__global__ __launch_bounds__(128) void accum_final(float* __restrict__ out) {
    __shared__ int   smap[MAXN];
    __shared__ float wsh[MAXN];
    __shared__ float swn[4], swd[4];
    __shared__ int   done;

    const int blk = blockIdx.x;              // 0..895
    const int cls = blk & (NCLS - 1);
    const int t   = blk >> 7;                // 0..6
    const int tid = threadIdx.x;
    const int n2  = g_n2[cls];

    float pnum = 0.f, pden = 0.f;
    if (n2 > 1) {
        for (int r = tid; r < n2; r += 128) {
            smap[r] = g_smap[cls * MAXN + r];
            wsh[r]  = g_w[(t * NCLS + cls) * MAXN + r];
        }
        __syncthreads();
        const size_t mbp = (size_t)(t * NCLS + cls) * MAXN * MAXN;
        const size_t mbc = (size_t)((t + 1) * NCLS + cls) * MAXN * MAXN;
        const float* sp  = g_sim + (size_t)(t * NCLS + cls) * MAXN * MAXN;
        const float* sc  = g_sim + (size_t)((t + 1) * NCLS + cls) * MAXN * MAXN;
        for (int p = tid; p < n2 * n2; p += 128) {
            int i = p / n2, j = p % n2;
            if (i == j) continue;
            int o  = i * MAXN + j;
            int ml = g_msk[mbp + o];
            int mc = g_msk[mbc + o];
            if (ml | mc) {
                int go = smap[i] * MAXN + smap[j];
                float w  = wsh[i] * wsh[j];
                float al = ml ? sp[go] : 0.f;    // A = sim * M (masked sims > 0)
                float ac = mc ? sc[go] : 0.f;
                float d  = ac - al;
                pnum += d * d * w;
                pden += w;
            }
        }
    }
#pragma unroll
    for (int o = 16; o; o >>= 1) {
        pnum += __shfl_xor_sync(0xffffffffu, pnum, o);
        pden += __shfl_xor_sync(0xffffffffu, pden, o);
    }
    if ((tid & 31) == 0) { swn[tid >> 5] = pnum; swd[tid >> 5] = pden; }
    __syncthreads();
    if (tid == 0) {
        g_pnum[blk] = swn[0] + swn[1] + swn[2] + swn[3];
        g_pden[blk] = swd[0] + swd[1] + swd[2] + swd[3];
        __threadfence();
        int old = atomicAdd(&g_ctr, 1);
        done = (old == NT * NCLS - 1) ? 1 : 0;
    }
    __syncthreads();
    if (!done) return;

    // last block: deterministic combine of all 896 partials
    __shared__ float red[128];
    __shared__ float tnum[NT], tden[NT];
    for (int t2 = 0; t2 < NT; t2++) {
        red[tid] = g_pnum[t2 * NCLS + tid];
        __syncthreads();
        for (int s = 64; s; s >>= 1) { if (tid < s) red[tid] += red[tid + s]; __syncthreads(); }
        if (tid == 0) tnum[t2] = red[0];
        __syncthreads();
        red[tid] = g_pden[t2 * NCLS + tid];
        __syncthreads();
        for (int s = 64; s; s >>= 1) { if (tid < s) red[tid] += red[tid + s]; __syncthreads(); }
        if (tid == 0) tden[t2] = red[0];
        __syncthreads();
    }
    if (tid == 0) {
        float raw = 0.f;
        for (int t2 = 0; t2 < NT; t2++)
            if (tden[t2] > 0.f)                       // M_eff.sum() > 0 <=> any edge
                raw += tnum[t2] / fmaxf(tden[t2], 1e-8f);
        out[0] = 16.0f * (raw / 7.0f);                // LAMBDA_ALIGN_K * raw / (L-1)
        g_ctr = 0;                                    // reset for next graph replay
    }
}

extern "C" void kernel_launch(void* const* d_in, const int* in_sizes, int n_in,
                              void* d_out, int out_size) {
    const float* feats  = (const float*)d_in[0];
    const int*   labels = (const int*)d_in[1];   // int32 or int64; detected at runtime
    const int*   sids   = (const int*)d_in[2];
    float*       out    = (float*)d_out;

    const int DYN = SCAP * DPAD * 16;            // 55.7 KB padded stage
    cudaFuncSetAttribute(sims_kernel, cudaFuncAttributeMaxDynamicSharedMemorySize, DYN);

    sims_kernel<<<LYR * NCLS, 256, DYN>>>(feats, labels, sids);
    subset_kernel<<<NCLS, 256>>>();
    knn_kernel<<<LYR * NCLS, 256>>>();
    accum_final<<<NT * NCLS, 128>>>(out);
}